// round 2
// baseline (speedup 1.0000x reference)
#include <cuda_runtime.h>

#define NNODES 50000
#define NEDGES 600000
#define NRBF   50
#define DDIM   128
#define CUTOFF_F 5.0f
#define PI_F 3.14159265358979f

// Scratch for segment_sum result (no cudaMalloc allowed)
__device__ float g_xint[NNODES * DDIM];

// ---------------------------------------------------------------------------
// Kernel 1: zero the scatter accumulator
// ---------------------------------------------------------------------------
__global__ void zero_kernel() {
    int i = blockIdx.x * blockDim.x + threadIdx.x;
    const int n = NNODES * DDIM / 4;
    float4* p = reinterpret_cast<float4*>(g_xint);
    float4 z = make_float4(0.f, 0.f, 0.f, 0.f);
    for (; i < n; i += gridDim.x * blockDim.x) p[i] = z;
}

// ---------------------------------------------------------------------------
// Kernel 2: edge stage
//   per edge e: x_edge[d] = (sum_r rbf[e][r]*W_e[d][r] + b_e[d]) * cutoff(dist[e])
//   msg[d] = emb[node_type[src[e]]][d] * x_edge[d]
//   atomicAdd(g_xint[dst[e]][d], msg[d])
// blockDim = 128 (thread t owns output dim d=t). W_e row kept in registers.
// ---------------------------------------------------------------------------
#define EPB 8  // edges staged per block-iteration

__global__ __launch_bounds__(128) void edge_kernel(
    const float* __restrict__ rbf,
    const float* __restrict__ dist,
    const int*   __restrict__ src,
    const int*   __restrict__ dst,
    const int*   __restrict__ node_type,
    const float* __restrict__ emb,
    const float* __restrict__ W_e,
    const float* __restrict__ b_e)
{
    __shared__ float rbf_s[EPB * NRBF];
    __shared__ float w_s[EPB];
    __shared__ int   src_s[EPB];
    __shared__ int   dst_s[EPB];

    const int t = threadIdx.x;  // output dim

    // Hoist this thread's W_e row into registers (loop-invariant across edges)
    float wreg[NRBF];
#pragma unroll
    for (int r = 0; r < NRBF; ++r) wreg[r] = W_e[t * NRBF + r];
    const float bias = b_e[t];

    const int iters = NEDGES / EPB;  // 75000, exact
    for (int it = blockIdx.x; it < iters; it += gridDim.x) {
        const int e0 = it * EPB;
        // Stage EPB rbf rows (coalesced) + per-edge scalars
        for (int i = t; i < EPB * NRBF; i += 128)
            rbf_s[i] = rbf[e0 * NRBF + i];
        if (t < EPB) {
            const int e = e0 + t;
            const float dd = dist[e];
            float w = 0.f;
            if (dd < CUTOFF_F)
                w = 0.5f * (cosf(dd * (PI_F / CUTOFF_F)) + 1.0f);
            w_s[t]   = w;
            src_s[t] = src[e];
            dst_s[t] = dst[e];
        }
        __syncthreads();

#pragma unroll
        for (int j = 0; j < EPB; ++j) {
            const float* rb = rbf_s + j * NRBF;
            float acc0 = bias, acc1 = 0.f;  // 2 accumulators: break dep chain
#pragma unroll
            for (int r = 0; r < NRBF; r += 2) {
                acc0 += rb[r]     * wreg[r];
                acc1 += rb[r + 1] * wreg[r + 1];
            }
            const float xe = (acc0 + acc1) * w_s[j];
            const int nt = node_type[src_s[j]];
            const float xa = emb[nt * DDIM + t];        // broadcast nt, coalesced d
            atomicAdd(&g_xint[dst_s[j] * DDIM + t], xa * xe);  // RED.F32 (no return)
        }
        __syncthreads();
    }
}

// ---------------------------------------------------------------------------
// Kernel 3: combine
//   out[n][d] = b_c[d] + sum_{k<128} x_nodes[n][k]*W_c[d][k]
//                      + sum_{k<128} g_xint[n][k]*W_c[d][128+k]
// W_c staged fully in smem ([128][257] padded, conflict-free). Each thread
// owns one output dim and 8 nodes (8 accumulators -> LDS:FFMA ~ 1:8).
// ---------------------------------------------------------------------------
#define NB 8  // nodes per block-iteration
#define W_STRIDE 257
#define COMBINE_SMEM ((DDIM * W_STRIDE + NB * 2 * DDIM) * sizeof(float))

__global__ __launch_bounds__(128) void combine_kernel(
    const float* __restrict__ x_nodes,
    const float* __restrict__ W_c,
    const float* __restrict__ b_c,
    float* __restrict__ out)
{
    extern __shared__ float sm[];
    float* W_s = sm;                        // [128][257]
    float* xr  = sm + DDIM * W_STRIDE;      // [NB][256]

    const int t = threadIdx.x;  // output dim

    // Stage full W_c once per block (padded stride -> conflict-free reads)
    for (int i = t; i < DDIM * 2 * DDIM; i += 128) {
        const int d = i >> 8, k = i & 255;
        W_s[d * W_STRIDE + k] = W_c[i];
    }
    const float bias = b_c[t];
    __syncthreads();

    const float* wrow = W_s + t * W_STRIDE;
    const int iters = NNODES / NB;  // 6250, exact
    for (int it = blockIdx.x; it < iters; it += gridDim.x) {
        const int n0 = it * NB;
        // Stage NB concatenated rows: [x_nodes | g_xint]
        for (int i = t; i < NB * DDIM; i += 128) {
            const int j = i >> 7, k = i & 127;
            xr[j * 256 + k]       = x_nodes[(n0 + j) * DDIM + k];
            xr[j * 256 + 128 + k] = g_xint [(n0 + j) * DDIM + k];
        }
        __syncthreads();

        float acc[NB];
#pragma unroll
        for (int j = 0; j < NB; ++j) acc[j] = bias;

#pragma unroll 4
        for (int k = 0; k < 2 * DDIM; ++k) {
            const float w = wrow[k];        // 1 LDS (conflict-free)
#pragma unroll
            for (int j = 0; j < NB; ++j)    // 8 FFMA (xr reads broadcast)
                acc[j] += xr[j * 256 + k] * w;
        }
#pragma unroll
        for (int j = 0; j < NB; ++j)
            out[(n0 + j) * DDIM + t] = acc[j];
        __syncthreads();
    }
}

// ---------------------------------------------------------------------------
// Launch
// Inputs (metadata order):
//  0 node_type(i32)  1 x_nodes(f32)  2 src(i32)  3 dst(i32)  4 rbf_edges(f32)
//  5 dist(f32)       6 emb(f32)      7 W_e(f32)  8 b_e(f32)  9 W_c(f32) 10 b_c(f32)
// ---------------------------------------------------------------------------
extern "C" void kernel_launch(void* const* d_in, const int* in_sizes, int n_in,
                              void* d_out, int out_size) {
    const int*   node_type = (const int*)  d_in[0];
    const float* x_nodes   = (const float*)d_in[1];
    const int*   src       = (const int*)  d_in[2];
    const int*   dst       = (const int*)  d_in[3];
    const float* rbf       = (const float*)d_in[4];
    const float* dist      = (const float*)d_in[5];
    const float* emb       = (const float*)d_in[6];
    const float* W_e       = (const float*)d_in[7];
    const float* b_e       = (const float*)d_in[8];
    const float* W_c       = (const float*)d_in[9];
    const float* b_c       = (const float*)d_in[10];
    float* out = (float*)d_out;

    int sms = 148;
    cudaDeviceGetAttribute(&sms, cudaDevAttrMultiProcessorCount, 0);

    cudaFuncSetAttribute(combine_kernel,
                         cudaFuncAttributeMaxDynamicSharedMemorySize,
                         (int)COMBINE_SMEM);

    zero_kernel<<<512, 256>>>();
    edge_kernel<<<2048, 128>>>(rbf, dist, src, dst, node_type, emb, W_e, b_e);
    combine_kernel<<<sms, 128, COMBINE_SMEM>>>(x_nodes, W_c, b_c, out);
}